// round 1
// baseline (speedup 1.0000x reference)
#include <cuda_runtime.h>

// SigNet: depth-4 path signature (C=8 incl. time channel) + linear head.
// Kernel 1: per-batch sequential Chen scan, barrier-free per-thread state.
// Kernel 2: split-k tiled FP32 GEMM  out_part = y @ W^T
// Kernel 3: split-k reduction + bias.

#define NB      128
#define SLEN    1024
#define CIN     7
#define CCH     8
#define SIGCH   4680            // 8 + 64 + 512 + 4096
#define YSTRIDE 4704            // padded to multiple of 32 (pad stays zero)
#define DOUT    256
#define KSPLIT  7
#define KCHUNK  672             // 21 * 32 ; 7 * 672 = 4704

__device__ float g_y[NB * YSTRIDE];              // signatures (zero-init; pad rewritten to 0)
__device__ float g_part[KSPLIT * NB * DOUT];     // GEMM split-k partials

// ---------------------------------------------------------------------------
// Kernel 1: signature scan. 1 CTA per batch, 256 threads.
// Thread t owns (a,b) = (t>>5, (t>>2)&7) and c in {2*(t&3), 2*(t&3)+1}.
// Registers: s1 (level1[a]), s2 (level2[ab]), s3[2] (level3[abc]),
//            sig4[16] (level4[abc][0..7] for both c).
// ---------------------------------------------------------------------------
__global__ __launch_bounds__(256, 1) void sig_scan_kernel(const float* __restrict__ inp)
{
    __shared__ float vs[SLEN][CCH];   // 32 KB: per-step increments

    const int b   = blockIdx.x;
    const int tid = threadIdx.x;

    // Build increments: v[t][0] = time diff, v[t][1..7] = diff of inp.
    // Basepoint 0: first increment is the raw first sample.
    const float dt = 1.0f / 1023.0f;
    const float* x = inp + (size_t)b * SLEN * CIN;
    for (int i = tid; i < SLEN * CIN; i += 256) {
        int t = i / CIN, c = i - t * CIN;
        float cur  = x[i];
        float prev = (t == 0) ? 0.0f : x[i - CIN];
        vs[t][c + 1] = cur - prev;
    }
    for (int t = tid; t < SLEN; t += 256) {
        vs[t][0] = (t == 0) ? 0.0f : ((float)t * dt - (float)(t - 1) * dt);
    }
    __syncthreads();

    const int ab = tid >> 2;            // 0..63
    const int a  = ab >> 3;             // 0..7
    const int bb = ab & 7;              // 0..7
    const int c0 = (tid & 3) * 2;       // 0,2,4,6

    float s1 = 0.0f, s2 = 0.0f, s30 = 0.0f, s31 = 0.0f;
    float sig4[16];
#pragma unroll
    for (int i = 0; i < 16; i++) sig4[i] = 0.0f;

    const float inv24 = 1.0f / 24.0f;
    const float inv6  = 1.0f / 6.0f;

#pragma unroll 2
    for (int t = 0; t < SLEN; t++) {
        float vv[8];
        *(float4*)&vv[0] = *(const float4*)&vs[t][0];
        *(float4*)&vv[4] = *(const float4*)&vs[t][4];
        float va = vs[t][a];
        float vb = vs[t][bb];
        float2 vc = *(const float2*)&vs[t][c0];

        // Shared-across-c scalars (use OLD s1):
        float t6 = fmaf(s1, inv6, va * inv24);   // v_a/24 + s1/6
        float uu = fmaf(s1, 0.5f, va * inv6);    // v_a/6  + s1/2

        // ---- c = c0 ----
        {
            float vbc = vb * vc.x;
            float vch = vc.x * 0.5f;
            float K = fmaf(vbc, t6, s30);        // uses OLD s3, s2
            K = fmaf(s2, vch, K);
            s30 = fmaf(vbc, uu, s30);
            s30 = fmaf(s2, vc.x, s30);
#pragma unroll
            for (int d = 0; d < 8; d++)
                sig4[d] = fmaf(K, vv[d], sig4[d]);
        }
        // ---- c = c0+1 ----
        {
            float vbc = vb * vc.y;
            float vch = vc.y * 0.5f;
            float K = fmaf(vbc, t6, s31);
            K = fmaf(s2, vch, K);
            s31 = fmaf(vbc, uu, s31);
            s31 = fmaf(s2, vc.y, s31);
#pragma unroll
            for (int d = 0; d < 8; d++)
                sig4[8 + d] = fmaf(K, vv[d], sig4[8 + d]);
        }

        // Level-2 / level-1 (redundant per-thread copies; use OLD s1):
        float w = va * vb;
        s2 = fmaf(w, 0.5f, s2);
        s2 = fmaf(s1, vb, s2);
        s1 += va;
    }

    // Write signature: y = [L1(8) | L2(64) | L3(512) | L4(4096)]
    float* y = g_y + (size_t)b * YSTRIDE;
#pragma unroll
    for (int d = 0; d < 8; d++) y[584 + ab * 64 + c0 * 8 + d]       = sig4[d];
#pragma unroll
    for (int d = 0; d < 8; d++) y[584 + ab * 64 + (c0 + 1) * 8 + d] = sig4[8 + d];
    y[72 + ab * 8 + c0]     = s30;
    y[72 + ab * 8 + c0 + 1] = s31;
    if ((tid & 3) == 0)  y[8 + ab] = s2;     // one writer per (a,b)
    if ((tid & 31) == 0) y[a] = s1;          // one writer per a
    if (tid < YSTRIDE - SIGCH) y[SIGCH + tid] = 0.0f;   // keep pad at zero
}

// ---------------------------------------------------------------------------
// Kernel 2: split-k GEMM partials. grid = (16 col-groups, KSPLIT).
// CTA computes 128 batch-rows x 16 out-cols over KCHUNK of k.
// ---------------------------------------------------------------------------
__global__ __launch_bounds__(256, 1) void gemm_part_kernel(const float* __restrict__ W)
{
    __shared__ float ys[128][32];
    __shared__ float ws[16][33];   // padded: conflict-free column reads

    const int tid = threadIdx.x;
    const int cg = blockIdx.x;     // col group: cols cg*16 .. cg*16+15
    const int sp = blockIdx.y;     // k split
    const int kbase = sp * KCHUNK;

    const int cp = tid & 7;        // col pair within group: cols 2cp, 2cp+1
    const int rg = tid >> 3;       // 0..31 ; rows rg + 32*j, j<4

    float acc00 = 0.f, acc01 = 0.f, acc02 = 0.f, acc03 = 0.f;
    float acc10 = 0.f, acc11 = 0.f, acc12 = 0.f, acc13 = 0.f;

    for (int kc = 0; kc < KCHUNK; kc += 32) {
        const int k0 = kbase + kc;
        // load y tile: 128 x 32
#pragma unroll
        for (int ii = 0; ii < 4; ii++) {
            int lin = tid + 256 * ii;           // 0..1023
            int r = lin >> 3, seg = lin & 7;
            float4 val = *(const float4*)&g_y[r * YSTRIDE + k0 + seg * 4];
            *(float4*)&ys[r][seg * 4] = val;
        }
        // load W tile: 16 x 32 (guard k < SIGCH; pad region contributes 0)
#pragma unroll
        for (int ii = 0; ii < 2; ii++) {
            int lin = tid + 256 * ii;           // 0..511
            int r = lin >> 5, cc = lin & 31;
            int k = k0 + cc;
            ws[r][cc] = (k < SIGCH) ? W[(cg * 16 + r) * SIGCH + k] : 0.0f;
        }
        __syncthreads();
#pragma unroll
        for (int kk = 0; kk < 32; kk += 2) {
            float2 w0 = *(const float2*)&ws[2 * cp][kk];
            float2 w1 = *(const float2*)&ws[2 * cp + 1][kk];
            float2 y0 = *(const float2*)&ys[rg][kk];
            float2 y1 = *(const float2*)&ys[rg + 32][kk];
            float2 y2 = *(const float2*)&ys[rg + 64][kk];
            float2 y3 = *(const float2*)&ys[rg + 96][kk];
            acc00 = fmaf(y0.x, w0.x, acc00); acc00 = fmaf(y0.y, w0.y, acc00);
            acc01 = fmaf(y1.x, w0.x, acc01); acc01 = fmaf(y1.y, w0.y, acc01);
            acc02 = fmaf(y2.x, w0.x, acc02); acc02 = fmaf(y2.y, w0.y, acc02);
            acc03 = fmaf(y3.x, w0.x, acc03); acc03 = fmaf(y3.y, w0.y, acc03);
            acc10 = fmaf(y0.x, w1.x, acc10); acc10 = fmaf(y0.y, w1.y, acc10);
            acc11 = fmaf(y1.x, w1.x, acc11); acc11 = fmaf(y1.y, w1.y, acc11);
            acc12 = fmaf(y2.x, w1.x, acc12); acc12 = fmaf(y2.y, w1.y, acc12);
            acc13 = fmaf(y3.x, w1.x, acc13); acc13 = fmaf(y3.y, w1.y, acc13);
        }
        __syncthreads();
    }

    const int col0 = cg * 16 + 2 * cp;
    float* p = g_part + (size_t)sp * NB * DOUT;
    p[(rg +  0) * DOUT + col0]     = acc00;
    p[(rg + 32) * DOUT + col0]     = acc01;
    p[(rg + 64) * DOUT + col0]     = acc02;
    p[(rg + 96) * DOUT + col0]     = acc03;
    p[(rg +  0) * DOUT + col0 + 1] = acc10;
    p[(rg + 32) * DOUT + col0 + 1] = acc11;
    p[(rg + 64) * DOUT + col0 + 1] = acc12;
    p[(rg + 96) * DOUT + col0 + 1] = acc13;
}

// ---------------------------------------------------------------------------
// Kernel 3: reduce split-k partials + bias.
// ---------------------------------------------------------------------------
__global__ void reduce_bias_kernel(const float* __restrict__ bias, float* __restrict__ out)
{
    int idx = blockIdx.x * 256 + threadIdx.x;    // 0 .. 32767  ([b][o] row-major)
    float v = bias[idx & (DOUT - 1)];
#pragma unroll
    for (int s = 0; s < KSPLIT; s++)
        v += g_part[s * NB * DOUT + idx];
    out[idx] = v;
}

// ---------------------------------------------------------------------------
extern "C" void kernel_launch(void* const* d_in, const int* in_sizes, int n_in,
                              void* d_out, int out_size)
{
    (void)in_sizes; (void)n_in; (void)out_size;
    const float* inp  = (const float*)d_in[0];   // (128,1024,7)
    const float* W    = (const float*)d_in[1];   // (256,4680)
    const float* bias = (const float*)d_in[2];   // (256,)
    float* out = (float*)d_out;                  // (128,256)

    sig_scan_kernel<<<NB, 256>>>(inp);
    dim3 g2(16, KSPLIT);
    gemm_part_kernel<<<g2, 256>>>(W);
    reduce_bias_kernel<<<NB, 256>>>(bias, out);
}